// round 3
// baseline (speedup 1.0000x reference)
#include <cuda_runtime.h>
#include <math.h>
#include <stdint.h>

#define T_LEN 1024
#define BATCH 32
#define DIN   256
#define HID   512
#define G4    2048
#define NB    128
#define NT    512
#define BH    (BATCH*HID)

__device__ float g_gx[(long)T_LEN * BATCH * G4];   // [T][B][4H]
__device__ float g_hs[(long)T_LEN * BATCH * HID];  // [T][B][H]
__device__ unsigned g_arrive[NB];

// ---------------------------------------------------------------- helpers
__device__ __forceinline__ float fast_tanh(float x) {
  float y; asm("tanh.approx.f32 %0, %1;" : "=f"(y) : "f"(x)); return y;
}
__device__ __forceinline__ float fast_sig(float x) {
  return 0.5f * fast_tanh(0.5f * x) + 0.5f;
}
__device__ __forceinline__ void cp_async16(void* smem_dst, const void* gsrc) {
  uint32_t s = (uint32_t)__cvta_generic_to_shared(smem_dst);
  asm volatile("cp.async.cg.shared.global [%0], [%1], 16;\n" :: "r"(s), "l"(gsrc));
}
// packed dual-fp32 FMA (Blackwell f32x2 pipe): d.lo += a.lo*b.lo; d.hi += a.hi*b.hi
__device__ __forceinline__ void fma2(unsigned long long& d,
                                     unsigned long long a, unsigned long long b) {
  asm("fma.rn.f32x2 %0, %1, %2, %0;" : "+l"(d) : "l"(a), "l"(b));
}
__device__ __forceinline__ float hsum2(unsigned long long v) {
  return __uint_as_float((unsigned)v) + __uint_as_float((unsigned)(v >> 32));
}

// ---------------- phase 1: gx = x^T @ W_ih^T + (b_ih + b_hh) ----------------
__global__ __launch_bounds__(256) void gemm_input(
    const float* __restrict__ x, const float* __restrict__ Wih,
    const float* __restrict__ bih, const float* __restrict__ bhh) {
  __shared__ float xs[32][68];
  __shared__ float wsT[32][68];
  const int t0 = blockIdx.x * 64, n0 = blockIdx.y * 64, b = blockIdx.z;
  const int tid = threadIdx.x;
  const int tt4 = tid & 15, nn4 = tid >> 4;

  float acc[4][4];
#pragma unroll
  for (int i = 0; i < 4; i++)
#pragma unroll
    for (int j = 0; j < 4; j++) acc[i][j] = 0.f;

  for (int d0 = 0; d0 < DIN; d0 += 32) {
#pragma unroll
    for (int r = 0; r < 32; r += 4) {
      int dd = r + (tid >> 6);
      int tt = tid & 63;
      xs[dd][tt] = x[((long)b * DIN + d0 + dd) * T_LEN + t0 + tt];
    }
#pragma unroll
    for (int r = 0; r < 64; r += 8) {
      int nn = r + (tid >> 5);
      int dd = tid & 31;
      wsT[dd][nn] = Wih[(long)(n0 + nn) * DIN + d0 + dd];
    }
    __syncthreads();
#pragma unroll
    for (int dd = 0; dd < 32; dd++) {
      float4 a = *(const float4*)&xs[dd][tt4 * 4];
      float4 w = *(const float4*)&wsT[dd][nn4 * 4];
      acc[0][0] += a.x * w.x; acc[0][1] += a.x * w.y; acc[0][2] += a.x * w.z; acc[0][3] += a.x * w.w;
      acc[1][0] += a.y * w.x; acc[1][1] += a.y * w.y; acc[1][2] += a.y * w.z; acc[1][3] += a.y * w.w;
      acc[2][0] += a.z * w.x; acc[2][1] += a.z * w.y; acc[2][2] += a.z * w.z; acc[2][3] += a.z * w.w;
      acc[3][0] += a.w * w.x; acc[3][1] += a.w * w.y; acc[3][2] += a.w * w.z; acc[3][3] += a.w * w.w;
    }
    __syncthreads();
  }
  const int n = n0 + nn4 * 4;
  float4 b1 = *(const float4*)&bih[n];
  float4 b2 = *(const float4*)&bhh[n];
  float4 bv = make_float4(b1.x + b2.x, b1.y + b2.y, b1.z + b2.z, b1.w + b2.w);
#pragma unroll
  for (int i = 0; i < 4; i++) {
    int t = t0 + tt4 * 4 + i;
    float4 o = make_float4(acc[i][0] + bv.x, acc[i][1] + bv.y,
                           acc[i][2] + bv.z, acc[i][3] + bv.w);
    *(float4*)&g_gx[(long)t * (BATCH * G4) + (long)b * G4 + n] = o;
  }
}

__global__ void init_bar() {
  ((volatile unsigned*)g_arrive)[threadIdx.x] = 0u;
}

__global__ void dummy_k() {}

// ---------------- phase 2: persistent recurrent scan (f32x2 K-packed) -------
// 128 blocks x 512 threads. Block owns hidden units j = blk*4 + {0..3}, i.e.
// 16 W_hh rows (r = gate*4 + jj) resident in SMEM for all 1024 steps.
// Warp (16) = bh(2) x ks(4) x gh(2): rows gh*8..+7, batches bh*16..+15,
// k-range ks*128..+127. Lane = rsub(4) x bsub(8): thread tile =
// 2 rows x 2 batches x 128 k, accumulated as f32x2 over k-pairs.
#define KW   516                       // W row stride (floats)
#define KH   516                       // h row stride (floats)
#define SM_W    (16 * KW)              // 8256
#define SM_H    (32 * KH + 8)          // 16520
#define SM_RED  (64 * 33)              // 2112  : red[ks(4)][row(16)][b(33pad)]
#define SM_GXS  (16 * 33)              // 528   : gxs[row(16)][b(33pad)]
#define SMEM_SCAN_FLOATS (SM_W + SM_H + SM_RED + SM_GXS)
#define SMEM_SCAN_BYTES  (SMEM_SCAN_FLOATS * 4)

__global__ __launch_bounds__(NT, 1) void lstm_scan(const float* __restrict__ Whh) {
  extern __shared__ float sm[];
  float* Wsm = sm;
  float* hsm = Wsm + SM_W;
  float* red = hsm + SM_H;
  float* gxs = red + SM_RED;

  const int tid = threadIdx.x, blk = blockIdx.x;
  const int wid = tid >> 5, lane = tid & 31;
  const int bh = wid & 1, ks = (wid >> 1) & 3, gh = wid >> 3;
  const int rsub = lane & 3, bsub = lane >> 2;
  const int r0 = gh * 8 + rsub * 2;
  const int b0 = bh * 16 + bsub * 2;
  const int kb = ks * 128;

  // persistent W_hh slice: row r = g*4+jj  <-  W_hh[g*512 + blk*4 + jj][:]
  for (int idx = tid; idx < 16 * HID; idx += NT) {
    int r = idx >> 9, k = idx & 511;
    int g = r >> 2, jj = r & 3;
    Wsm[r * KW + k] = Whh[(long)(g * HID + blk * 4 + jj) * HID + k];
  }
  // zero h staging
  for (int i = tid; i < SM_H; i += NT) hsm[i] = 0.f;
  __syncthreads();

  // h row base with +4-float shift on (b>>3)&1 to spread banks
  const ulonglong2* w0p = (const ulonglong2*)(Wsm + r0 * KW + kb);
  const ulonglong2* w1p = (const ulonglong2*)(Wsm + (r0 + 1) * KW + kb);
  const ulonglong2* h0p = (const ulonglong2*)(hsm + b0 * KH + ((b0 >> 3) & 1) * 4 + kb);
  const ulonglong2* h1p = (const ulonglong2*)(hsm + (b0 + 1) * KH + (((b0 + 1) >> 3) & 1) * 4 + kb);

  const int rb_j = tid >> 5, rb_b = tid & 31;  // reducer mapping (tid<128): j=rb_j, b=rb_b
  float c_reg = 0.f;

  for (int t = 0; t < T_LEN; t++) {
    // ---- gx prefetch: [b][g][4jj] float4, stored transposed gxs[g*4+jj][b]
    float4 gxv;
    if (tid < 128) {
      int b = tid >> 2, g = tid & 3;
      gxv = *(const float4*)&g_gx[(long)t * (BATCH * G4) + (long)b * G4 + g * HID + blk * 4];
    }
    // ---- stage h(t-1) via cp.async (layout [b][k], 128B rows) ----
    if (t > 0) {
      const float* src = g_hs + (long)(t - 1) * BH;
#pragma unroll
      for (int c = 0; c < 8; c++) {
        int f = c * NT + tid;          // 16B chunk id, 0..4095
        int b = f >> 7;                // 128 chunks per batch row
        int koff = (f & 127) * 4;
        cp_async16(hsm + b * KH + ((b >> 3) & 1) * 4 + koff, src + f * 4);
      }
      asm volatile("cp.async.commit_group;\n");
    }
    if (tid < 128) {
      int b = tid >> 2, g = tid & 3;
      gxs[(g * 4 + 0) * 33 + b] = gxv.x;
      gxs[(g * 4 + 1) * 33 + b] = gxv.y;
      gxs[(g * 4 + 2) * 33 + b] = gxv.z;
      gxs[(g * 4 + 3) * 33 + b] = gxv.w;
    }
    if (t > 0) asm volatile("cp.async.wait_group 0;\n" ::: "memory");
    __syncthreads();

    // ---- f32x2 GEMM partial: 2 rows x 2 batches x 128 k ----
    unsigned long long a00 = 0ull, a01 = 0ull, a10 = 0ull, a11 = 0ull;
#pragma unroll 8
    for (int i = 0; i < 32; i++) {
      ulonglong2 wa = w0p[i];
      ulonglong2 wb = w1p[i];
      ulonglong2 ha = h0p[i];
      ulonglong2 hb = h1p[i];
      fma2(a00, wa.x, ha.x); fma2(a00, wa.y, ha.y);
      fma2(a01, wa.x, hb.x); fma2(a01, wa.y, hb.y);
      fma2(a10, wb.x, ha.x); fma2(a10, wb.y, ha.y);
      fma2(a11, wb.x, hb.x); fma2(a11, wb.y, hb.y);
    }
    // ---- spill partial sums: red[ks][row][b] ----
    {
      float* rp = red + (ks * 16 + r0) * 33;
      rp[b0]          = hsum2(a00);
      rp[b0 + 1]      = hsum2(a01);
      rp[33 + b0]     = hsum2(a10);
      rp[33 + b0 + 1] = hsum2(a11);
    }
    __syncthreads();

    // ---- reduce + gates: thread tid<128 owns (j = blk*4 + rb_j, b = rb_b)
    if (tid < 128) {
      float s0 = gxs[(0 * 4 + rb_j) * 33 + rb_b];
      float s1 = gxs[(1 * 4 + rb_j) * 33 + rb_b];
      float s2 = gxs[(2 * 4 + rb_j) * 33 + rb_b];
      float s3 = gxs[(3 * 4 + rb_j) * 33 + rb_b];
#pragma unroll
      for (int p = 0; p < 4; p++) {
        const float* q = red + p * 16 * 33 + rb_b;
        s0 += q[(0 * 4 + rb_j) * 33];
        s1 += q[(1 * 4 + rb_j) * 33];
        s2 += q[(2 * 4 + rb_j) * 33];
        s3 += q[(3 * 4 + rb_j) * 33];
      }
      float ig = fast_sig(s0);
      float fg = fast_sig(s1);
      float gg = fast_tanh(s2);
      float og = fast_sig(s3);
      c_reg = fg * c_reg + ig * gg;
      float h = og * fast_tanh(c_reg);
      g_hs[(long)t * BH + rb_b * HID + blk * 4 + rb_j] = h;
    }

    // ---- grid barrier: per-block flag + warp-0 sweep ----
    __syncthreads();
    if (tid == 0) {
      __threadfence();
      ((volatile unsigned*)g_arrive)[blk] = (unsigned)(t + 1);
    }
    if (tid < 32) {
      const unsigned target = (unsigned)(t + 1);
      const volatile unsigned* fl = (const volatile unsigned*)g_arrive;
      bool ok;
      do {
        unsigned a = fl[tid], b = fl[tid + 32], c = fl[tid + 64], d = fl[tid + 96];
        ok = __all_sync(0xffffffffu,
                        (a >= target) && (b >= target) && (c >= target) && (d >= target));
      } while (!ok);
    }
    __syncthreads();
  }
}

// ---------------- phase 3: transpose hs[T][B][H] -> out[B][H][T] ------------
__global__ __launch_bounds__(256) void transpose_hs(float* __restrict__ out) {
  __shared__ float tile[32][33];
  const int t0 = blockIdx.x * 32, j0 = blockIdx.y * 32, b = blockIdx.z;
  const int tx = threadIdx.x, ty = threadIdx.y;
  for (int i = ty; i < 32; i += 8)
    tile[i][tx] = g_hs[(long)(t0 + i) * BH + (long)b * HID + j0 + tx];
  __syncthreads();
  for (int i = ty; i < 32; i += 8)
    out[((long)b * HID + j0 + i) * T_LEN + t0 + tx] = tile[tx][i];
}

// ---------------- launch ----------------
extern "C" void kernel_launch(void* const* d_in, const int* in_sizes, int n_in,
                              void* d_out, int out_size) {
  (void)in_sizes; (void)n_in; (void)out_size;
  const float* x   = (const float*)d_in[0];
  const float* Wih = (const float*)d_in[1];
  const float* Whh = (const float*)d_in[2];
  const float* bih = (const float*)d_in[3];
  const float* bhh = (const float*)d_in[4];
  float* out = (float*)d_out;

  cudaFuncSetAttribute(lstm_scan, cudaFuncAttributeMaxDynamicSharedMemorySize,
                       SMEM_SCAN_BYTES);

  dim3 g1(T_LEN / 64, G4 / 64, BATCH);
  gemm_input<<<g1, 256>>>(x, Wih, bih, bhh);          // launch 1
  init_bar<<<1, NB>>>();                               // launch 2
  dummy_k<<<1, 32>>>();                                // launch 3
  lstm_scan<<<NB, NT, SMEM_SCAN_BYTES>>>(Whh);         // launch 4  (ncu window)

  dim3 g3(T_LEN / 32, HID / 32, BATCH);
  transpose_hs<<<g3, dim3(32, 8)>>>(out);              // launch 5
}

// round 4
// speedup vs baseline: 1.5051x; 1.5051x over previous
#include <cuda_runtime.h>
#include <math.h>
#include <stdint.h>

#define T_LEN 1024
#define BATCH 32
#define DIN   256
#define HID   512
#define G4    2048
#define NB    128
#define NT    512
#define BH    (BATCH*HID)

__device__ float g_gx[(long)T_LEN * BATCH * G4];   // [T][B][4H]
__device__ float g_hs[(long)T_LEN * BATCH * HID];  // [T][B][H]
__device__ unsigned g_arrive[NB];
__device__ unsigned g_epoch;

// ---------------------------------------------------------------- helpers
__device__ __forceinline__ float fast_tanh(float x) {
  float y; asm("tanh.approx.f32 %0, %1;" : "=f"(y) : "f"(x)); return y;
}
__device__ __forceinline__ float fast_sig(float x) {
  return 0.5f * fast_tanh(0.5f * x) + 0.5f;
}
__device__ __forceinline__ void fma2(unsigned long long& d,
                                     unsigned long long a, unsigned long long b) {
  asm("fma.rn.f32x2 %0, %1, %2, %0;" : "+l"(d) : "l"(a), "l"(b));
}
__device__ __forceinline__ float hsum2(unsigned long long v) {
  return __uint_as_float((unsigned)v) + __uint_as_float((unsigned)(v >> 32));
}

// ---------------- phase 1: gx = x^T @ W_ih^T + (b_ih + b_hh) ----------------
__global__ __launch_bounds__(256) void gemm_input(
    const float* __restrict__ x, const float* __restrict__ Wih,
    const float* __restrict__ bih, const float* __restrict__ bhh) {
  __shared__ float xs[32][68];
  __shared__ float wsT[32][68];
  const int t0 = blockIdx.x * 64, n0 = blockIdx.y * 64, b = blockIdx.z;
  const int tid = threadIdx.x;
  const int tt4 = tid & 15, nn4 = tid >> 4;

  float acc[4][4];
#pragma unroll
  for (int i = 0; i < 4; i++)
#pragma unroll
    for (int j = 0; j < 4; j++) acc[i][j] = 0.f;

  for (int d0 = 0; d0 < DIN; d0 += 32) {
#pragma unroll
    for (int r = 0; r < 32; r += 4) {
      int dd = r + (tid >> 6);
      int tt = tid & 63;
      xs[dd][tt] = x[((long)b * DIN + d0 + dd) * T_LEN + t0 + tt];
    }
#pragma unroll
    for (int r = 0; r < 64; r += 8) {
      int nn = r + (tid >> 5);
      int dd = tid & 31;
      wsT[dd][nn] = Wih[(long)(n0 + nn) * DIN + d0 + dd];
    }
    __syncthreads();
#pragma unroll
    for (int dd = 0; dd < 32; dd++) {
      float4 a = *(const float4*)&xs[dd][tt4 * 4];
      float4 w = *(const float4*)&wsT[dd][nn4 * 4];
      acc[0][0] += a.x * w.x; acc[0][1] += a.x * w.y; acc[0][2] += a.x * w.z; acc[0][3] += a.x * w.w;
      acc[1][0] += a.y * w.x; acc[1][1] += a.y * w.y; acc[1][2] += a.y * w.z; acc[1][3] += a.y * w.w;
      acc[2][0] += a.z * w.x; acc[2][1] += a.z * w.y; acc[2][2] += a.z * w.z; acc[2][3] += a.z * w.w;
      acc[3][0] += a.w * w.x; acc[3][1] += a.w * w.y; acc[3][2] += a.w * w.z; acc[3][3] += a.w * w.w;
    }
    __syncthreads();
  }
  const int n = n0 + nn4 * 4;
  float4 b1 = *(const float4*)&bih[n];
  float4 b2 = *(const float4*)&bhh[n];
  float4 bv = make_float4(b1.x + b2.x, b1.y + b2.y, b1.z + b2.z, b1.w + b2.w);
#pragma unroll
  for (int i = 0; i < 4; i++) {
    int t = t0 + tt4 * 4 + i;
    float4 o = make_float4(acc[i][0] + bv.x, acc[i][1] + bv.y,
                           acc[i][2] + bv.z, acc[i][3] + bv.w);
    *(float4*)&g_gx[(long)t * (BATCH * G4) + (long)b * G4 + n] = o;
  }
}

__global__ void init_bar() {
  ((volatile unsigned*)g_arrive)[threadIdx.x] = 0u;
  if (threadIdx.x == 0) *(volatile unsigned*)&g_epoch = 0u;
}

__global__ void dummy_k() {}

// ---------------- phase 2: persistent recurrent scan ----------------
// 128 blocks x 512 threads; identical compute tiling to R3 (f32x2 K-packed).
// New: h staged via cp.async.bulk (32 x 2KB row copies -> mbarrier),
// two-level epoch barrier, hout + STG.128 h stores.
#define KW   516
#define KH   516
#define SM_W    (16 * KW)              // 8256
#define SM_H    (32 * KH + 8)          // 16520
#define SM_RED  (64 * 33)              // 2112
#define SM_GXS  (16 * 33)              // 528
#define SM_HOUT 128
#define SMEM_SCAN_FLOATS (SM_W + SM_H + SM_RED + SM_GXS + SM_HOUT + 8)
#define SMEM_SCAN_BYTES  (SMEM_SCAN_FLOATS * 4)

__global__ __launch_bounds__(NT, 1) void lstm_scan(const float* __restrict__ Whh) {
  extern __shared__ float sm[];
  float* Wsm  = sm;
  float* hsm  = Wsm + SM_W;
  float* red  = hsm + SM_H;
  float* gxs  = red + SM_RED;
  float* hout = gxs + SM_GXS;
  unsigned long long* mbar = (unsigned long long*)(hout + SM_HOUT);

  const int tid = threadIdx.x, blk = blockIdx.x;
  const int wid = tid >> 5, lane = tid & 31;
  const int bh = wid & 1, ks = (wid >> 1) & 3, gh = wid >> 3;
  const int rsub = lane & 3, bsub = lane >> 2;
  const int r0 = gh * 8 + rsub * 2;
  const int b0 = bh * 16 + bsub * 2;
  const int kb = ks * 128;
  const uint32_t mbar_addr = (uint32_t)__cvta_generic_to_shared(mbar);

  // persistent W_hh slice: row r = g*4+jj  <-  W_hh[g*512 + blk*4 + jj][:]
  for (int idx = tid; idx < 16 * HID; idx += NT) {
    int r = idx >> 9, k = idx & 511;
    int g = r >> 2, jj = r & 3;
    Wsm[r * KW + k] = Whh[(long)(g * HID + blk * 4 + jj) * HID + k];
  }
  for (int i = tid; i < SM_H; i += NT) hsm[i] = 0.f;
  if (tid == 0)
    asm volatile("mbarrier.init.shared.b64 [%0], 1;" :: "r"(mbar_addr));
  __syncthreads();

  const ulonglong2* w0p = (const ulonglong2*)(Wsm + r0 * KW + kb);
  const ulonglong2* w1p = (const ulonglong2*)(Wsm + (r0 + 1) * KW + kb);
  const ulonglong2* h0p = (const ulonglong2*)(hsm + b0 * KH + ((b0 >> 3) & 1) * 4 + kb);
  const ulonglong2* h1p = (const ulonglong2*)(hsm + (b0 + 1) * KH + (((b0 + 1) >> 3) & 1) * 4 + kb);

  const int rb_j = tid >> 5, rb_b = tid & 31;   // reducer mapping (tid<128)
  float c_reg = 0.f;
  int ph = 0;

  for (int t = 0; t < T_LEN; t++) {
    // ---- gx prefetch (regs) ----
    float4 gxv;
    if (tid < 128) {
      int b = tid >> 2, g = tid & 3;
      gxv = *(const float4*)&g_gx[(long)t * (BATCH * G4) + (long)b * G4 + g * HID + blk * 4];
    }

    if (t > 0) {
      // ---- barrier wait + bulk h copy issue (warp 0 only) ----
      if (tid < 32) {
        if (blk == 0) {
          const volatile unsigned* fl = (const volatile unsigned*)g_arrive;
          const unsigned tg = (unsigned)t;
          bool ok;
          do {
            unsigned a = fl[tid], b = fl[tid + 32], c = fl[tid + 64], d = fl[tid + 96];
            ok = __all_sync(0xffffffffu,
                            (a >= tg) && (b >= tg) && (c >= tg) && (d >= tg));
          } while (!ok);
          if (tid == 0) {
            __threadfence();
            *(volatile unsigned*)&g_epoch = tg;
          }
          __syncwarp();
        } else {
          if (tid == 0) {
            while (*(volatile unsigned*)&g_epoch < (unsigned)t) {}
          }
          __syncwarp();
        }
        asm volatile("fence.proxy.async;" ::: "memory");
        if (tid == 0)
          asm volatile("mbarrier.arrive.expect_tx.shared.b64 _, [%0], %1;"
                       :: "r"(mbar_addr), "r"(65536u));
        __syncwarp();
        {
          int b = tid;
          const float* src = g_hs + (long)(t - 1) * BH + b * HID;
          float* dst = hsm + b * KH + ((b >> 3) & 1) * 4;
          uint32_t d32 = (uint32_t)__cvta_generic_to_shared(dst);
          asm volatile(
            "cp.async.bulk.shared::cluster.global.mbarrier::complete_tx::bytes "
            "[%0], [%1], %2, [%3];"
            :: "r"(d32), "l"(src), "r"(2048u), "r"(mbar_addr) : "memory");
        }
      }
      // gx -> smem (transposed) while copy is in flight
      if (tid < 128) {
        int b = tid >> 2, g = tid & 3;
        gxs[(g * 4 + 0) * 33 + b] = gxv.x;
        gxs[(g * 4 + 1) * 33 + b] = gxv.y;
        gxs[(g * 4 + 2) * 33 + b] = gxv.z;
        gxs[(g * 4 + 3) * 33 + b] = gxv.w;
      }
      // all threads wait for h data
      {
        uint32_t done = 0;
        while (!done) {
          asm volatile(
            "{\n\t.reg .pred p;\n\t"
            "mbarrier.try_wait.parity.shared.b64 p, [%1], %2, 10000000;\n\t"
            "selp.b32 %0, 1, 0, p;\n\t}"
            : "=r"(done) : "r"(mbar_addr), "r"((unsigned)ph) : "memory");
        }
      }
      ph ^= 1;
    } else {
      if (tid < 128) {
        int b = tid >> 2, g = tid & 3;
        gxs[(g * 4 + 0) * 33 + b] = gxv.x;
        gxs[(g * 4 + 1) * 33 + b] = gxv.y;
        gxs[(g * 4 + 2) * 33 + b] = gxv.z;
        gxs[(g * 4 + 3) * 33 + b] = gxv.w;
      }
    }

    // ---- f32x2 GEMM partial: 2 rows x 2 batches x 128 k ----
    unsigned long long a00 = 0ull, a01 = 0ull, a10 = 0ull, a11 = 0ull;
#pragma unroll 8
    for (int i = 0; i < 32; i++) {
      ulonglong2 wa = w0p[i];
      ulonglong2 wb = w1p[i];
      ulonglong2 ha = h0p[i];
      ulonglong2 hb = h1p[i];
      fma2(a00, wa.x, ha.x); fma2(a00, wa.y, ha.y);
      fma2(a01, wa.x, hb.x); fma2(a01, wa.y, hb.y);
      fma2(a10, wb.x, ha.x); fma2(a10, wb.y, ha.y);
      fma2(a11, wb.x, hb.x); fma2(a11, wb.y, hb.y);
    }
    {
      float* rp = red + (ks * 16 + r0) * 33;
      rp[b0]          = hsum2(a00);
      rp[b0 + 1]      = hsum2(a01);
      rp[33 + b0]     = hsum2(a10);
      rp[33 + b0 + 1] = hsum2(a11);
    }
    __syncthreads();

    // ---- reduce + gates ----
    if (tid < 128) {
      float s0 = gxs[(0 * 4 + rb_j) * 33 + rb_b];
      float s1 = gxs[(1 * 4 + rb_j) * 33 + rb_b];
      float s2 = gxs[(2 * 4 + rb_j) * 33 + rb_b];
      float s3 = gxs[(3 * 4 + rb_j) * 33 + rb_b];
#pragma unroll
      for (int p = 0; p < 4; p++) {
        const float* q = red + p * 16 * 33 + rb_b;
        s0 += q[(0 * 4 + rb_j) * 33];
        s1 += q[(1 * 4 + rb_j) * 33];
        s2 += q[(2 * 4 + rb_j) * 33];
        s3 += q[(3 * 4 + rb_j) * 33];
      }
      float ig = fast_sig(s0);
      float fg = fast_sig(s1);
      float gg = fast_tanh(s2);
      float og = fast_sig(s3);
      c_reg = fg * c_reg + ig * gg;
      float h = og * fast_tanh(c_reg);
      hout[rb_b * 4 + rb_j] = h;
    }
    __syncthreads();

    // ---- warp 0: vector h store + flag ----
    if (tid < 32) {
      float4 hv = *(const float4*)&hout[tid * 4];
      *(float4*)&g_hs[(long)t * BH + tid * HID + blk * 4] = hv;
      __threadfence();
      __syncwarp();
      if (tid == 0)
        ((volatile unsigned*)g_arrive)[blk] = (unsigned)(t + 1);
    }
  }
}

// ---------------- phase 3: transpose hs[T][B][H] -> out[B][H][T] ------------
__global__ __launch_bounds__(256) void transpose_hs(float* __restrict__ out) {
  __shared__ float tile[32][33];
  const int t0 = blockIdx.x * 32, j0 = blockIdx.y * 32, b = blockIdx.z;
  const int tx = threadIdx.x, ty = threadIdx.y;
  for (int i = ty; i < 32; i += 8)
    tile[i][tx] = g_hs[(long)(t0 + i) * BH + (long)b * HID + j0 + tx];
  __syncthreads();
  for (int i = ty; i < 32; i += 8)
    out[((long)b * HID + j0 + i) * T_LEN + t0 + tx] = tile[tx][i];
}

// ---------------- launch ----------------
extern "C" void kernel_launch(void* const* d_in, const int* in_sizes, int n_in,
                              void* d_out, int out_size) {
  (void)in_sizes; (void)n_in; (void)out_size;
  const float* x   = (const float*)d_in[0];
  const float* Wih = (const float*)d_in[1];
  const float* Whh = (const float*)d_in[2];
  const float* bih = (const float*)d_in[3];
  const float* bhh = (const float*)d_in[4];
  float* out = (float*)d_out;

  cudaFuncSetAttribute(lstm_scan, cudaFuncAttributeMaxDynamicSharedMemorySize,
                       SMEM_SCAN_BYTES);

  dim3 g1(T_LEN / 64, G4 / 64, BATCH);
  gemm_input<<<g1, 256>>>(x, Wih, bih, bhh);          // launch 1
  init_bar<<<1, NB>>>();                               // launch 2
  dummy_k<<<1, 32>>>();                                // launch 3
  lstm_scan<<<NB, NT, SMEM_SCAN_BYTES>>>(Whh);         // launch 4 (ncu window)

  dim3 g3(T_LEN / 32, HID / 32, BATCH);
  transpose_hs<<<g3, dim3(32, 8)>>>(out);              // launch 5
}

// round 5
// speedup vs baseline: 1.6384x; 1.0886x over previous
#include <cuda_runtime.h>
#include <math.h>
#include <stdint.h>

#define T_LEN 1024
#define BATCH 32
#define DIN   256
#define HID   512
#define G4    2048
#define NB    128
#define NT    512
#define BH    (BATCH*HID)

__device__ float g_gx[(long)T_LEN * BATCH * G4];   // [T][B][4H]
__device__ float g_hs[(long)T_LEN * BATCH * HID];  // [T][B][H]
__device__ unsigned g_cnt;                          // monotonic arrival counter

// ---------------------------------------------------------------- helpers
__device__ __forceinline__ float fast_tanh(float x) {
  float y; asm("tanh.approx.f32 %0, %1;" : "=f"(y) : "f"(x)); return y;
}
__device__ __forceinline__ float fast_sig(float x) {
  return 0.5f * fast_tanh(0.5f * x) + 0.5f;
}
__device__ __forceinline__ void fma2(unsigned long long& d,
                                     unsigned long long a, unsigned long long b) {
  asm("fma.rn.f32x2 %0, %1, %2, %0;" : "+l"(d) : "l"(a), "l"(b));
}
__device__ __forceinline__ float hsum2(unsigned long long v) {
  return __uint_as_float((unsigned)v) + __uint_as_float((unsigned)(v >> 32));
}

// ---------------- phase 1: gx = x^T @ W_ih^T + (b_ih + b_hh) ----------------
__global__ __launch_bounds__(256) void gemm_input(
    const float* __restrict__ x, const float* __restrict__ Wih,
    const float* __restrict__ bih, const float* __restrict__ bhh) {
  __shared__ float xs[32][68];
  __shared__ float wsT[32][68];
  const int t0 = blockIdx.x * 64, n0 = blockIdx.y * 64, b = blockIdx.z;
  const int tid = threadIdx.x;
  const int tt4 = tid & 15, nn4 = tid >> 4;

  float acc[4][4];
#pragma unroll
  for (int i = 0; i < 4; i++)
#pragma unroll
    for (int j = 0; j < 4; j++) acc[i][j] = 0.f;

  for (int d0 = 0; d0 < DIN; d0 += 32) {
#pragma unroll
    for (int r = 0; r < 32; r += 4) {
      int dd = r + (tid >> 6);
      int tt = tid & 63;
      xs[dd][tt] = x[((long)b * DIN + d0 + dd) * T_LEN + t0 + tt];
    }
#pragma unroll
    for (int r = 0; r < 64; r += 8) {
      int nn = r + (tid >> 5);
      int dd = tid & 31;
      wsT[dd][nn] = Wih[(long)(n0 + nn) * DIN + d0 + dd];
    }
    __syncthreads();
#pragma unroll
    for (int dd = 0; dd < 32; dd++) {
      float4 a = *(const float4*)&xs[dd][tt4 * 4];
      float4 w = *(const float4*)&wsT[dd][nn4 * 4];
      acc[0][0] += a.x * w.x; acc[0][1] += a.x * w.y; acc[0][2] += a.x * w.z; acc[0][3] += a.x * w.w;
      acc[1][0] += a.y * w.x; acc[1][1] += a.y * w.y; acc[1][2] += a.y * w.z; acc[1][3] += a.y * w.w;
      acc[2][0] += a.z * w.x; acc[2][1] += a.z * w.y; acc[2][2] += a.z * w.z; acc[2][3] += a.z * w.w;
      acc[3][0] += a.w * w.x; acc[3][1] += a.w * w.y; acc[3][2] += a.w * w.z; acc[3][3] += a.w * w.w;
    }
    __syncthreads();
  }
  const int n = n0 + nn4 * 4;
  float4 b1 = *(const float4*)&bih[n];
  float4 b2 = *(const float4*)&bhh[n];
  float4 bv = make_float4(b1.x + b2.x, b1.y + b2.y, b1.z + b2.z, b1.w + b2.w);
#pragma unroll
  for (int i = 0; i < 4; i++) {
    int t = t0 + tt4 * 4 + i;
    float4 o = make_float4(acc[i][0] + bv.x, acc[i][1] + bv.y,
                           acc[i][2] + bv.z, acc[i][3] + bv.w);
    *(float4*)&g_gx[(long)t * (BATCH * G4) + (long)b * G4 + n] = o;
  }
}

__global__ void init_bar() {
  if (threadIdx.x == 0) *(volatile unsigned*)&g_cnt = 0u;
}

__global__ void dummy_k() {}

// ---------------- phase 2: persistent recurrent scan ----------------
// 128 blocks x 512 threads; f32x2 K-packed compute (unchanged from R4).
// Sync: single monotonic L2 counter (RED.ADD arrival, 1-word acquire poll).
#define KW   516
#define KH   516
#define SM_W    (16 * KW)              // 8256
#define SM_H    (32 * KH + 8)          // 16520
#define SM_RED  (64 * 33)              // 2112
#define SM_GXS  (16 * 33)              // 528
#define SM_HOUT 128
#define SMEM_SCAN_FLOATS (SM_W + SM_H + SM_RED + SM_GXS + SM_HOUT + 8)
#define SMEM_SCAN_BYTES  (SMEM_SCAN_FLOATS * 4)

__global__ __launch_bounds__(NT, 1) void lstm_scan(const float* __restrict__ Whh) {
  extern __shared__ float sm[];
  float* Wsm  = sm;
  float* hsm  = Wsm + SM_W;
  float* red  = hsm + SM_H;
  float* gxs  = red + SM_RED;
  float* hout = gxs + SM_GXS;
  unsigned long long* mbar = (unsigned long long*)(hout + SM_HOUT);

  const int tid = threadIdx.x, blk = blockIdx.x;
  const int wid = tid >> 5, lane = tid & 31;
  const int bh = wid & 1, ks = (wid >> 1) & 3, gh = wid >> 3;
  const int rsub = lane & 3, bsub = lane >> 2;
  const int r0 = gh * 8 + rsub * 2;
  const int b0 = bh * 16 + bsub * 2;
  const int kb = ks * 128;
  const uint32_t mbar_addr = (uint32_t)__cvta_generic_to_shared(mbar);

  // persistent W_hh slice: row r = g*4+jj  <-  W_hh[g*512 + blk*4 + jj][:]
  for (int idx = tid; idx < 16 * HID; idx += NT) {
    int r = idx >> 9, k = idx & 511;
    int g = r >> 2, jj = r & 3;
    Wsm[r * KW + k] = Whh[(long)(g * HID + blk * 4 + jj) * HID + k];
  }
  for (int i = tid; i < SM_H; i += NT) hsm[i] = 0.f;
  if (tid == 0)
    asm volatile("mbarrier.init.shared.b64 [%0], 1;" :: "r"(mbar_addr));
  __syncthreads();

  const ulonglong2* w0p = (const ulonglong2*)(Wsm + r0 * KW + kb);
  const ulonglong2* w1p = (const ulonglong2*)(Wsm + (r0 + 1) * KW + kb);
  const ulonglong2* h0p = (const ulonglong2*)(hsm + b0 * KH + ((b0 >> 3) & 1) * 4 + kb);
  const ulonglong2* h1p = (const ulonglong2*)(hsm + (b0 + 1) * KH + (((b0 + 1) >> 3) & 1) * 4 + kb);

  const int rb_j = tid >> 5, rb_b = tid & 31;   // reducer mapping (tid<128)
  float c_reg = 0.f;
  int ph = 0;

  for (int t = 0; t < T_LEN; t++) {
    // ---- gx prefetch (regs, independent of h) ----
    float4 gxv;
    if (tid < 128) {
      int b = tid >> 2, g = tid & 3;
      gxv = *(const float4*)&g_gx[(long)t * (BATCH * G4) + (long)b * G4 + g * HID + blk * 4];
    }

    if (t > 0) {
      // ---- warp 0: single-word arrival poll, then bulk h fetch ----
      if (tid < 32) {
        const unsigned tgt = 128u * (unsigned)t;
        unsigned v;
        do {
          v = *(volatile unsigned*)&g_cnt;
        } while (v < tgt);
        __threadfence();                          // acquire ordering
        asm volatile("fence.proxy.async;" ::: "memory");
        if (tid == 0)
          asm volatile("mbarrier.arrive.expect_tx.shared.b64 _, [%0], %1;"
                       :: "r"(mbar_addr), "r"(65536u));
        __syncwarp();
        {
          int b = tid;
          const float* src = g_hs + (long)(t - 1) * BH + b * HID;
          float* dst = hsm + b * KH + ((b >> 3) & 1) * 4;
          uint32_t d32 = (uint32_t)__cvta_generic_to_shared(dst);
          asm volatile(
            "cp.async.bulk.shared::cluster.global.mbarrier::complete_tx::bytes "
            "[%0], [%1], %2, [%3];"
            :: "r"(d32), "l"(src), "r"(2048u), "r"(mbar_addr) : "memory");
        }
      }
      // gx -> smem (transposed) while copy is in flight
      if (tid < 128) {
        int b = tid >> 2, g = tid & 3;
        gxs[(g * 4 + 0) * 33 + b] = gxv.x;
        gxs[(g * 4 + 1) * 33 + b] = gxv.y;
        gxs[(g * 4 + 2) * 33 + b] = gxv.z;
        gxs[(g * 4 + 3) * 33 + b] = gxv.w;
      }
      // all threads wait for h data
      {
        uint32_t done = 0;
        while (!done) {
          asm volatile(
            "{\n\t.reg .pred p;\n\t"
            "mbarrier.try_wait.parity.shared.b64 p, [%1], %2, 10000000;\n\t"
            "selp.b32 %0, 1, 0, p;\n\t}"
            : "=r"(done) : "r"(mbar_addr), "r"((unsigned)ph) : "memory");
        }
      }
      ph ^= 1;
    } else {
      if (tid < 128) {
        int b = tid >> 2, g = tid & 3;
        gxs[(g * 4 + 0) * 33 + b] = gxv.x;
        gxs[(g * 4 + 1) * 33 + b] = gxv.y;
        gxs[(g * 4 + 2) * 33 + b] = gxv.z;
        gxs[(g * 4 + 3) * 33 + b] = gxv.w;
      }
    }

    // ---- f32x2 GEMM partial: 2 rows x 2 batches x 128 k ----
    unsigned long long a00 = 0ull, a01 = 0ull, a10 = 0ull, a11 = 0ull;
#pragma unroll 8
    for (int i = 0; i < 32; i++) {
      ulonglong2 wa = w0p[i];
      ulonglong2 wb = w1p[i];
      ulonglong2 ha = h0p[i];
      ulonglong2 hb = h1p[i];
      fma2(a00, wa.x, ha.x); fma2(a00, wa.y, ha.y);
      fma2(a01, wa.x, hb.x); fma2(a01, wa.y, hb.y);
      fma2(a10, wb.x, ha.x); fma2(a10, wb.y, ha.y);
      fma2(a11, wb.x, hb.x); fma2(a11, wb.y, hb.y);
    }
    {
      float* rp = red + (ks * 16 + r0) * 33;
      rp[b0]          = hsum2(a00);
      rp[b0 + 1]      = hsum2(a01);
      rp[33 + b0]     = hsum2(a10);
      rp[33 + b0 + 1] = hsum2(a11);
    }
    __syncthreads();

    // ---- reduce + gates (tid<128 owns (j = blk*4 + rb_j, b = rb_b)) ----
    if (tid < 128) {
      float s0 = gxs[(0 * 4 + rb_j) * 33 + rb_b];
      float s1 = gxs[(1 * 4 + rb_j) * 33 + rb_b];
      float s2 = gxs[(2 * 4 + rb_j) * 33 + rb_b];
      float s3 = gxs[(3 * 4 + rb_j) * 33 + rb_b];
#pragma unroll
      for (int p = 0; p < 4; p++) {
        const float* q = red + p * 16 * 33 + rb_b;
        s0 += q[(0 * 4 + rb_j) * 33];
        s1 += q[(1 * 4 + rb_j) * 33];
        s2 += q[(2 * 4 + rb_j) * 33];
        s3 += q[(3 * 4 + rb_j) * 33];
      }
      float ig = fast_sig(s0);
      float fg = fast_sig(s1);
      float gg = fast_tanh(s2);
      float og = fast_sig(s3);
      c_reg = fg * c_reg + ig * gg;
      float h = og * fast_tanh(c_reg);
      hout[rb_b * 4 + rb_j] = h;
      // reducer-only barrier (warps 0-3); non-reducers gated by next mbarrier
      asm volatile("bar.sync 1, 128;" ::: "memory");
      if (tid < 32) {
        float4 hv = *(const float4*)&hout[tid * 4];
        *(float4*)&g_hs[(long)t * BH + tid * HID + blk * 4] = hv;
        __syncwarp();
        if (tid == 0) {
          __threadfence();                 // release: h stores before arrival
          atomicAdd(&g_cnt, 1u);           // RED.E.ADD (no return)
        }
      }
    }
  }
}

// ---------------- phase 3: transpose hs[T][B][H] -> out[B][H][T] ------------
__global__ __launch_bounds__(256) void transpose_hs(float* __restrict__ out) {
  __shared__ float tile[32][33];
  const int t0 = blockIdx.x * 32, j0 = blockIdx.y * 32, b = blockIdx.z;
  const int tx = threadIdx.x, ty = threadIdx.y;
  for (int i = ty; i < 32; i += 8)
    tile[i][tx] = g_hs[(long)(t0 + i) * BH + (long)b * HID + j0 + tx];
  __syncthreads();
  for (int i = ty; i < 32; i += 8)
    out[((long)b * HID + j0 + i) * T_LEN + t0 + tx] = tile[tx][i];
}

// ---------------- launch ----------------
extern "C" void kernel_launch(void* const* d_in, const int* in_sizes, int n_in,
                              void* d_out, int out_size) {
  (void)in_sizes; (void)n_in; (void)out_size;
  const float* x   = (const float*)d_in[0];
  const float* Wih = (const float*)d_in[1];
  const float* Whh = (const float*)d_in[2];
  const float* bih = (const float*)d_in[3];
  const float* bhh = (const float*)d_in[4];
  float* out = (float*)d_out;

  cudaFuncSetAttribute(lstm_scan, cudaFuncAttributeMaxDynamicSharedMemorySize,
                       SMEM_SCAN_BYTES);

  dim3 g1(T_LEN / 64, G4 / 64, BATCH);
  gemm_input<<<g1, 256>>>(x, Wih, bih, bhh);          // launch 1
  init_bar<<<1, 32>>>();                               // launch 2
  dummy_k<<<1, 32>>>();                                // launch 3
  lstm_scan<<<NB, NT, SMEM_SCAN_BYTES>>>(Whh);         // launch 4 (ncu window)

  dim3 g3(T_LEN / 32, HID / 32, BATCH);
  transpose_hs<<<g3, dim3(32, 8)>>>(out);              // launch 5
}

// round 6
// speedup vs baseline: 2.0203x; 1.2331x over previous
#include <cuda_runtime.h>
#include <math.h>
#include <stdint.h>

#define T_LEN 1024
#define BATCH 32
#define DIN   256
#define HID   512
#define G4    2048
#define NB    128
#define NT    512
#define BH    (BATCH*HID)

__device__ float g_gx[(long)T_LEN * BATCH * G4];          // [T][B][4H]
__device__ float g_hs4[(long)T_LEN * NB * BATCH * 4];     // [T][blk][b][4]
__device__ unsigned g_cnt4[256];                          // counters at q*64

// ---------------------------------------------------------------- helpers
__device__ __forceinline__ float fast_tanh(float x) {
  float y; asm("tanh.approx.f32 %0, %1;" : "=f"(y) : "f"(x)); return y;
}
__device__ __forceinline__ float fast_sig(float x) {
  return 0.5f * fast_tanh(0.5f * x) + 0.5f;
}
__device__ __forceinline__ void fma2(unsigned long long& d,
                                     unsigned long long a, unsigned long long b) {
  asm("fma.rn.f32x2 %0, %1, %2, %0;" : "+l"(d) : "l"(a), "l"(b));
}
__device__ __forceinline__ float hsum2(unsigned long long v) {
  return __uint_as_float((unsigned)v) + __uint_as_float((unsigned)(v >> 32));
}

// ---------------- phase 1: gx = x^T @ W_ih^T + (b_ih + b_hh) ----------------
__global__ __launch_bounds__(256) void gemm_input(
    const float* __restrict__ x, const float* __restrict__ Wih,
    const float* __restrict__ bih, const float* __restrict__ bhh) {
  __shared__ float xs[32][68];
  __shared__ float wsT[32][68];
  const int t0 = blockIdx.x * 64, n0 = blockIdx.y * 64, b = blockIdx.z;
  const int tid = threadIdx.x;
  const int tt4 = tid & 15, nn4 = tid >> 4;

  float acc[4][4];
#pragma unroll
  for (int i = 0; i < 4; i++)
#pragma unroll
    for (int j = 0; j < 4; j++) acc[i][j] = 0.f;

  for (int d0 = 0; d0 < DIN; d0 += 32) {
#pragma unroll
    for (int r = 0; r < 32; r += 4) {
      int dd = r + (tid >> 6);
      int tt = tid & 63;
      xs[dd][tt] = x[((long)b * DIN + d0 + dd) * T_LEN + t0 + tt];
    }
#pragma unroll
    for (int r = 0; r < 64; r += 8) {
      int nn = r + (tid >> 5);
      int dd = tid & 31;
      wsT[dd][nn] = Wih[(long)(n0 + nn) * DIN + d0 + dd];
    }
    __syncthreads();
#pragma unroll
    for (int dd = 0; dd < 32; dd++) {
      float4 a = *(const float4*)&xs[dd][tt4 * 4];
      float4 w = *(const float4*)&wsT[dd][nn4 * 4];
      acc[0][0] += a.x * w.x; acc[0][1] += a.x * w.y; acc[0][2] += a.x * w.z; acc[0][3] += a.x * w.w;
      acc[1][0] += a.y * w.x; acc[1][1] += a.y * w.y; acc[1][2] += a.y * w.z; acc[1][3] += a.y * w.w;
      acc[2][0] += a.z * w.x; acc[2][1] += a.z * w.y; acc[2][2] += a.z * w.z; acc[2][3] += a.z * w.w;
      acc[3][0] += a.w * w.x; acc[3][1] += a.w * w.y; acc[3][2] += a.w * w.z; acc[3][3] += a.w * w.w;
    }
    __syncthreads();
  }
  const int n = n0 + nn4 * 4;
  float4 b1 = *(const float4*)&bih[n];
  float4 b2 = *(const float4*)&bhh[n];
  float4 bv = make_float4(b1.x + b2.x, b1.y + b2.y, b1.z + b2.z, b1.w + b2.w);
#pragma unroll
  for (int i = 0; i < 4; i++) {
    int t = t0 + tt4 * 4 + i;
    float4 o = make_float4(acc[i][0] + bv.x, acc[i][1] + bv.y,
                           acc[i][2] + bv.z, acc[i][3] + bv.w);
    *(float4*)&g_gx[(long)t * (BATCH * G4) + (long)b * G4 + n] = o;
  }
}

__global__ void init_bar() {
  if (threadIdx.x < 4) *(volatile unsigned*)&g_cnt4[threadIdx.x * 64] = 0u;
}

__global__ void dummy_k() {}

// ---------------- phase 2: persistent recurrent scan (chunk-pipelined) ------
// 128 blocks x 512 threads. Block owns units j = blk*4+{0..3} (16 W rows in
// SMEM). Warp wid: bh = wid&1 (batch half), gh = (wid>>1)&1 (gate half),
// ksw = wid>>2 (k-chunk 0..3). Each SMSP hosts one warp of each chunk.
// h interchange: g_hs4[t][blk][b][4]; chunk q = blocks [q*32,(q+1)*32) =
// 16KB contiguous, fetched by ONE cp.async.bulk into smem chunk q, gated by
// counter q (32 arrivals) and mbar[q].
#define KW      516
#define SM_W    (16 * KW)              // 8256
#define CHUNK_F 4096                   // floats per smem h chunk (16KB)
#define SM_H    (4 * CHUNK_F)          // 16384
#define SM_RED  (64 * 33)              // 2112
#define SM_GXS  (16 * 33)              // 528
#define SM_HOUT 128
#define SMEM_SCAN_FLOATS (SM_W + SM_H + SM_RED + SM_GXS + SM_HOUT + 16)
#define SMEM_SCAN_BYTES  (SMEM_SCAN_FLOATS * 4)

__global__ __launch_bounds__(NT, 1) void lstm_scan(const float* __restrict__ Whh) {
  extern __shared__ float sm[];
  float* Wsm  = sm;
  float* hsm  = Wsm + SM_W;
  float* red  = hsm + SM_H;
  float* gxs  = red + SM_RED;
  float* hout = gxs + SM_GXS;
  unsigned long long* mbar = (unsigned long long*)(hout + SM_HOUT);  // 4 mbarriers

  const int tid = threadIdx.x, blk = blockIdx.x;
  const int wid = tid >> 5, lane = tid & 31;
  const int bh = wid & 1, gh = (wid >> 1) & 1, ksw = wid >> 2;
  const int rsub = lane & 3, bsub = lane >> 2;
  const int r0 = gh * 8 + rsub * 2;
  const int b0 = bh * 16 + bsub * 2;
  const int kb = ksw * 128;
  const int q_own = blk >> 5;                       // producer group
  const uint32_t mb_base = (uint32_t)__cvta_generic_to_shared(mbar);

  // persistent W_hh slice: row r = g*4+jj  <-  W_hh[g*512 + blk*4 + jj][:]
  for (int idx = tid; idx < 16 * HID; idx += NT) {
    int r = idx >> 9, k = idx & 511;
    int g = r >> 2, jj = r & 3;
    Wsm[r * KW + k] = Whh[(long)(g * HID + blk * 4 + jj) * HID + k];
  }
  for (int i = tid; i < SM_H; i += NT) hsm[i] = 0.f;
  if (tid < 4)
    asm volatile("mbarrier.init.shared.b64 [%0], 1;" :: "r"(mb_base + tid * 8));
  __syncthreads();

  const ulonglong2* w0p = (const ulonglong2*)(Wsm + r0 * KW + kb);
  const ulonglong2* w1p = (const ulonglong2*)(Wsm + (r0 + 1) * KW + kb);
  // h chunk layout: hsm[ksw*4096 + (k4*32 + b)*4]
  const float* hb0 = hsm + ksw * CHUNK_F + b0 * 4;
  const float* hb1 = hsm + ksw * CHUNK_F + (b0 + 1) * 4;

  const int rb_j = tid >> 5, rb_b = tid & 31;   // reducer mapping (tid<128)
  float c_reg = 0.f;

  for (int t = 0; t < T_LEN; t++) {
    // ---- gx prefetch (regs, independent of h) ----
    float4 gxv;
    if (tid < 128) {
      int b = tid >> 2, g = tid & 3;
      gxv = *(const float4*)&g_gx[(long)t * (BATCH * G4) + (long)b * G4 + g * HID + blk * 4];
    }

    if (t > 0) {
      // ---- chunk-q fetch: warp q*4 lane 0 polls counter q, issues 16KB TMA
      if (lane == 0 && (wid & 3) == 0) {
        const int q = ksw;
        const unsigned tgt = 32u * (unsigned)t;
        unsigned v;
        do {
          asm volatile("ld.acquire.gpu.global.u32 %0, [%1];"
                       : "=r"(v) : "l"(&g_cnt4[q * 64]));
        } while (v < tgt);
        asm volatile("fence.proxy.async;" ::: "memory");
        uint32_t mb = mb_base + q * 8;
        asm volatile("mbarrier.arrive.expect_tx.shared.b64 _, [%0], %1;"
                     :: "r"(mb), "r"(16384u));
        const float* src = g_hs4 + ((long)(t - 1) * NB + q * 32) * (BATCH * 4);
        uint32_t d32 = (uint32_t)__cvta_generic_to_shared(hsm + q * CHUNK_F);
        asm volatile(
          "cp.async.bulk.shared::cluster.global.mbarrier::complete_tx::bytes "
          "[%0], [%1], %2, [%3];"
          :: "r"(d32), "l"(src), "r"(16384u), "r"(mb) : "memory");
      }
      // gx -> smem transposed (reducers; self-ordered w.r.t. their own reads)
      if (tid < 128) {
        int b = tid >> 2, g = tid & 3;
        gxs[(g * 4 + 0) * 33 + b] = gxv.x;
        gxs[(g * 4 + 1) * 33 + b] = gxv.y;
        gxs[(g * 4 + 2) * 33 + b] = gxv.z;
        gxs[(g * 4 + 3) * 33 + b] = gxv.w;
      }
      // wait own chunk only
      {
        uint32_t mb = mb_base + ksw * 8;
        uint32_t done = 0;
        unsigned phase = (unsigned)((t - 1) & 1);
        while (!done) {
          asm volatile(
            "{\n\t.reg .pred p;\n\t"
            "mbarrier.try_wait.parity.shared.b64 p, [%1], %2, 10000000;\n\t"
            "selp.b32 %0, 1, 0, p;\n\t}"
            : "=r"(done) : "r"(mb), "r"(phase) : "memory");
        }
      }
    } else {
      if (tid < 128) {
        int b = tid >> 2, g = tid & 3;
        gxs[(g * 4 + 0) * 33 + b] = gxv.x;
        gxs[(g * 4 + 1) * 33 + b] = gxv.y;
        gxs[(g * 4 + 2) * 33 + b] = gxv.z;
        gxs[(g * 4 + 3) * 33 + b] = gxv.w;
      }
    }

    // ---- f32x2 GEMM partial: 2 rows x 2 batches x 128 k ----
    unsigned long long a00 = 0ull, a01 = 0ull, a10 = 0ull, a11 = 0ull;
#pragma unroll 8
    for (int i = 0; i < 32; i++) {
      ulonglong2 wa = w0p[i];
      ulonglong2 wb = w1p[i];
      ulonglong2 ha = *(const ulonglong2*)(hb0 + i * 128);
      ulonglong2 hb = *(const ulonglong2*)(hb1 + i * 128);
      fma2(a00, wa.x, ha.x); fma2(a00, wa.y, ha.y);
      fma2(a01, wa.x, hb.x); fma2(a01, wa.y, hb.y);
      fma2(a10, wb.x, ha.x); fma2(a10, wb.y, ha.y);
      fma2(a11, wb.x, hb.x); fma2(a11, wb.y, hb.y);
    }
    {
      float* rp = red + (ksw * 16 + r0) * 33;
      rp[b0]          = hsum2(a00);
      rp[b0 + 1]      = hsum2(a01);
      rp[33 + b0]     = hsum2(a10);
      rp[33 + b0 + 1] = hsum2(a11);
    }
    __syncthreads();

    // ---- reduce + gates (tid<128 owns (j = blk*4 + rb_j, b = rb_b)) ----
    if (tid < 128) {
      float s0 = gxs[(0 * 4 + rb_j) * 33 + rb_b];
      float s1 = gxs[(1 * 4 + rb_j) * 33 + rb_b];
      float s2 = gxs[(2 * 4 + rb_j) * 33 + rb_b];
      float s3 = gxs[(3 * 4 + rb_j) * 33 + rb_b];
#pragma unroll
      for (int p = 0; p < 4; p++) {
        const float* q = red + p * 16 * 33 + rb_b;
        s0 += q[(0 * 4 + rb_j) * 33];
        s1 += q[(1 * 4 + rb_j) * 33];
        s2 += q[(2 * 4 + rb_j) * 33];
        s3 += q[(3 * 4 + rb_j) * 33];
      }
      float ig = fast_sig(s0);
      float fg = fast_sig(s1);
      float gg = fast_tanh(s2);
      float og = fast_sig(s3);
      c_reg = fg * c_reg + ig * gg;
      float h = og * fast_tanh(c_reg);
      hout[rb_b * 4 + rb_j] = h;
      asm volatile("bar.sync 1, 128;" ::: "memory");
      if (tid < 32) {
        // coalesced 512B burst: g_hs4[t][blk][b=tid][0..3]
        float4 hv = *(const float4*)&hout[tid * 4];
        *(float4*)&g_hs4[(((long)t * NB + blk) * BATCH + tid) * 4] = hv;
        __syncwarp();
        if (tid == 0)
          asm volatile("red.release.gpu.global.add.u32 [%0], %1;"
                       :: "l"(&g_cnt4[q_own * 64]), "r"(1u) : "memory");
      }
    }
  }
}

// ---------------- phase 3: hs4[T][blk][b][4] -> out[B][H][T] ---------------
__global__ __launch_bounds__(256) void transpose_hs(float* __restrict__ out) {
  __shared__ float tile[32][33];
  const int t0 = blockIdx.x * 32, j0 = blockIdx.y * 32, b = blockIdx.z;
  const int tx = threadIdx.x, ty = threadIdx.y;
  for (int i = ty; i < 32; i += 8) {
    int j = j0 + tx;
    tile[i][tx] = g_hs4[(((long)(t0 + i) * NB + (j >> 2)) * BATCH + b) * 4 + (j & 3)];
  }
  __syncthreads();
  for (int i = ty; i < 32; i += 8)
    out[((long)b * HID + j0 + i) * T_LEN + t0 + tx] = tile[tx][i];
}

// ---------------- launch ----------------
extern "C" void kernel_launch(void* const* d_in, const int* in_sizes, int n_in,
                              void* d_out, int out_size) {
  (void)in_sizes; (void)n_in; (void)out_size;
  const float* x   = (const float*)d_in[0];
  const float* Wih = (const float*)d_in[1];
  const float* Whh = (const float*)d_in[2];
  const float* bih = (const float*)d_in[3];
  const float* bhh = (const float*)d_in[4];
  float* out = (float*)d_out;

  cudaFuncSetAttribute(lstm_scan, cudaFuncAttributeMaxDynamicSharedMemorySize,
                       SMEM_SCAN_BYTES);

  dim3 g1(T_LEN / 64, G4 / 64, BATCH);
  gemm_input<<<g1, 256>>>(x, Wih, bih, bhh);          // launch 1
  init_bar<<<1, 32>>>();                               // launch 2
  dummy_k<<<1, 32>>>();                                // launch 3
  lstm_scan<<<NB, NT, SMEM_SCAN_BYTES>>>(Whh);         // launch 4 (ncu window)

  dim3 g3(T_LEN / 32, HID / 32, BATCH);
  transpose_hs<<<g3, dim3(32, 8)>>>(out);              // launch 5
}